// round 16
// baseline (speedup 1.0000x reference)
#include <cuda_runtime.h>
#include <cuda_bf16.h>

#define N_WAVES 128
#define TPB 128

__device__ __forceinline__ float sinap(float a) {
    float r; asm("sin.approx.f32 %0, %1;" : "=f"(r) : "f"(a)); return r;
}

__global__ void __launch_bounds__(TPB, 16)
wave_kernel(const float2* __restrict__ x2,   // one point per thread
            const float* __restrict__ freqs,
            const float* __restrict__ rots,
            const float* __restrict__ coeffs,
            float* __restrict__ out, int n) {
    // All waves raw-radian MUFU path: swp[w] = (gx, gy, ph, A), radians.
    // 3 FFMA + 1 MUFU per point per wave — the FFMA floor for this problem.
    __shared__ float4 swp[N_WAVES];
    if (threadIdx.x < N_WAVES) {
        int w = threadIdx.x;
        float f  = freqs[w];
        float r  = rots[w];
        float c0 = coeffs[2 * w];
        float c1 = coeffs[2 * w + 1];
        float sr, cr;
        sincosf(r, &sr, &cr);
        float A  = sqrtf(c0 * c0 + c1 * c1);
        float ph = atan2f(c1, c0);                 // radians
        const float two_pi = 6.283185307179586f;
        swp[w] = make_float4(two_pi * f * cr, two_pi * f * sr, ph, A);
    }
    __syncthreads();

    int p = blockIdx.x * TPB + threadIdx.x;        // one point per thread
    float2 a = (p < n) ? x2[p] : make_float2(0.f, 0.f);
    float x = a.x, y = a.y;
    float acc = 0.f;

#pragma unroll 8
    for (int i = 0; i < N_WAVES; i++) {
        float4 q = swp[i];   // LDS.128 broadcast, conflict-free
        float u = fmaf(x, q.x, fmaf(y, q.y, q.z));
        acc = fmaf(q.w, sinap(u), acc);
    }

    if (p < n) out[p] = acc;
}

extern "C" void kernel_launch(void* const* d_in, const int* in_sizes, int n_in,
                              void* d_out, int out_size) {
    const float* x      = (const float*)d_in[0];  // [N,2]
    const float* freqs  = (const float*)d_in[1];  // [W,1]
    const float* rots   = (const float*)d_in[2];  // [W,1]
    const float* coeffs = (const float*)d_in[3];  // [W,2]
    float* out = (float*)d_out;                   // [N,1]

    int n = in_sizes[0] / 2;

    int blocks = (n + TPB - 1) / TPB;
    wave_kernel<<<blocks, TPB>>>((const float2*)x, freqs, rots, coeffs, out, n);
}

// round 17
// speedup vs baseline: 1.1098x; 1.1098x over previous
#include <cuda_runtime.h>
#include <cuda_bf16.h>

#define N_WAVES 128
#define TPB 64

__device__ __forceinline__ float sinap(float a) {
    float r; asm("sin.approx.f32 %0, %1;" : "=f"(r) : "f"(a)); return r;
}

__global__ void __launch_bounds__(TPB, 28)
wave_kernel(const float4* __restrict__ x4,   // 2 points per float4
            const float* __restrict__ freqs,
            const float* __restrict__ rots,
            const float* __restrict__ coeffs,
            float2* __restrict__ out2, int n) {
    // All waves raw-radian MUFU path: swp[w] = (gx, gy, ph, A), radians.
    // 3 FFMA + 1 MUFU per point per wave — the FFMA floor for this problem.
    __shared__ float4 swp[N_WAVES];
#pragma unroll
    for (int w = threadIdx.x; w < N_WAVES; w += TPB) {
        float f  = freqs[w];
        float r  = rots[w];
        float c0 = coeffs[2 * w];
        float c1 = coeffs[2 * w + 1];
        float sr, cr;
        sincosf(r, &sr, &cr);
        float A  = sqrtf(c0 * c0 + c1 * c1);
        float ph = atan2f(c1, c0);                 // radians
        const float two_pi = 6.283185307179586f;
        swp[w] = make_float4(two_pi * f * cr, two_pi * f * sr, ph, A);
    }
    __syncthreads();

    int pairsTotal = n >> 1;                      // number of float4s
    int p = blockIdx.x * TPB + threadIdx.x;       // one float4 per thread

    float4 a = (p < pairsTotal) ? x4[p] : make_float4(0.f, 0.f, 0.f, 0.f);
    float x0 = a.x, y0 = a.y, x1 = a.z, y1 = a.w;
    float acc0 = 0.f, acc1 = 0.f;

#pragma unroll 4
    for (int i = 0; i < N_WAVES; i++) {
        float4 q = swp[i];   // LDS.128 broadcast, conflict-free
        float u0 = fmaf(x0, q.x, fmaf(y0, q.y, q.z));
        float u1 = fmaf(x1, q.x, fmaf(y1, q.y, q.z));
        acc0 = fmaf(q.w, sinap(u0), acc0);
        acc1 = fmaf(q.w, sinap(u1), acc1);
    }

    if (p < pairsTotal) out2[p] = make_float2(acc0, acc1);

    // Odd-n tail: single scalar point.
    if ((n & 1) && blockIdx.x == 0 && threadIdx.x == 0) {
        float tx = ((const float2*)x4)[n - 1].x;
        float ty = ((const float2*)x4)[n - 1].y;
        float ac = 0.f;
        for (int i = 0; i < N_WAVES; i++) {
            float4 q = swp[i];
            float u = fmaf(tx, q.x, fmaf(ty, q.y, q.z));
            ac = fmaf(q.w, sinap(u), ac);
        }
        ((float*)out2)[n - 1] = ac;
    }
}

extern "C" void kernel_launch(void* const* d_in, const int* in_sizes, int n_in,
                              void* d_out, int out_size) {
    const float* x      = (const float*)d_in[0];  // [N,2]
    const float* freqs  = (const float*)d_in[1];  // [W,1]
    const float* rots   = (const float*)d_in[2];  // [W,1]
    const float* coeffs = (const float*)d_in[3];  // [W,2]
    float* out = (float*)d_out;                   // [N,1]

    int n = in_sizes[0] / 2;

    int pairs = (n + 1) / 2;                       // float4 count
    int blocks = (pairs + TPB - 1) / TPB;
    wave_kernel<<<blocks, TPB>>>((const float4*)x, freqs, rots, coeffs,
                                 (float2*)out, n);
}